// round 13
// baseline (speedup 1.0000x reference)
#include <cuda_runtime.h>
#include <cuda_bf16.h>
#include <math.h>
#include <stdint.h>

// Problem constants
constexpr int B  = 64;
constexpr int H  = 1024;
constexpr int E  = 1024;
constexpr int SEQ = 1024;
constexpr int V  = 50257;
constexpr long long BV = (long long)B * V;
constexpr int SPL = 8;                       // split-K for GRU gate GEMMs
constexpr int CATSPL = 16;                   // split-K for concat GEMM
constexpr int NB = 128;                      // out-gemm N tile
constexpr int NBLK  = (V + NB - 1) / NB;     // 393 col-blocks
constexpr int NBLKP = 400;                   // padded stride

// ---------------- scratch (static device memory; no allocs) ----------------
__device__ float g_gi[SPL * 3 * H * B];      // GRU input-gate partials  [split][row][b]
__device__ float g_gh[SPL * 3 * H * B];      // GRU hidden-gate partials
__device__ float g_hnew[B * H];              // new hidden state [b][h]
__device__ float g_pm[B * 16];               // attention chunk max
__device__ float g_pl[B * 16];               // attention chunk sum
__device__ float g_pctx[B * 16 * H];         // attention chunk context
__device__ float g_ctx[B * H];               // context [b][h]
__device__ float g_cpart[CATSPL * H * B];    // concat-gemm partials [split][n][b]
__device__ __nv_bfloat16 g_co_bf[B * H];     // concat_out (tanh) bf16 [b][n]
__device__ float2 g_plse[B * NBLKP];         // per-(row, colblock) softmax partials (m,l)

// ---------------- helpers ----------------
static __device__ __forceinline__ unsigned pack_bf2(float lo, float hi) {
    __nv_bfloat162 v = __floats2bfloat162_rn(lo, hi);
    return *reinterpret_cast<unsigned*>(&v);
}
// split fp32 pair into bf16 hi-plane word + bf16 residual word
static __device__ __forceinline__ void split2(float a, float b, unsigned& hi, unsigned& lo) {
    __nv_bfloat16 ha = __float2bfloat16(a), hb = __float2bfloat16(b);
    float ra = a - __bfloat162float(ha);
    float rb = b - __bfloat162float(hb);
    __nv_bfloat162 hv; hv.x = ha; hv.y = hb;
    hi = *reinterpret_cast<unsigned*>(&hv);
    lo = pack_bf2(ra, rb);
}
static __device__ __forceinline__ void ldm_x4(unsigned& r0, unsigned& r1,
                                              unsigned& r2, unsigned& r3, const void* p) {
    unsigned addr = (unsigned)__cvta_generic_to_shared(p);
    asm volatile("ldmatrix.sync.aligned.m8n8.x4.shared.b16 {%0,%1,%2,%3}, [%4];"
                 : "=r"(r0), "=r"(r1), "=r"(r2), "=r"(r3) : "r"(addr));
}
static __device__ __forceinline__ void mma16816(float* d, const unsigned* a,
                                                unsigned b0, unsigned b1) {
    asm volatile(
        "mma.sync.aligned.m16n8k16.row.col.f32.bf16.bf16.f32 "
        "{%0,%1,%2,%3}, {%4,%5,%6,%7}, {%8,%9}, {%0,%1,%2,%3};"
        : "+f"(d[0]), "+f"(d[1]), "+f"(d[2]), "+f"(d[3])
        : "r"(a[0]), "r"(a[1]), "r"(a[2]), "r"(a[3]), "r"(b0), "r"(b1));
}
static __device__ __forceinline__ void cp16(uint32_t dst_smem, const void* src) {
    asm volatile("cp.async.cg.shared.global [%0], [%1], 16;"
                 :: "r"(dst_smem), "l"(src) : "memory");
}
#define CP_COMMIT() asm volatile("cp.async.commit_group;" ::: "memory")
#define CP_WAIT1()  asm volatile("cp.async.wait_group 1;" ::: "memory")

// ---------------- small mma GEMMs with hi/lo bf16 (near-fp32 precision) ----------------
// C[64 x NTOT] = A[64 x KTOT] @ W[NTOT x KTOT]^T, split-K partials [split][n][64b].
// MODE 0: GRU pair (z=0: gi/emb-gather, z=1: gh/last_hidden).  MODE 2: concat GEMM.
// acc += Ahi@Bhi + Ahi@Blo + Alo@Bhi  (lo*lo dropped, ~2^-16 rel)
template<int MODE, int NTOT, int KTOT, int SPLITS>
__global__ __launch_bounds__(256) void mma_small(
    const int*   __restrict__ gidx,
    const float* __restrict__ emb,
    const float* __restrict__ lh,
    const float* __restrict__ w0,
    const float* __restrict__ w1)
{
    constexpr int KSPAN = KTOT / SPLITS;      // 128
    constexpr int NST   = KSPAN / 32;         // 4
    constexpr int ASTR  = KSPAN * 2 + 16;     // 272 B row stride per bf16 plane
    constexpr uint32_t APL    = 64u * ASTR;             // 17408 per A plane
    constexpr uint32_t OFF_BR2 = 2u * APL;              // 34816
    constexpr uint32_t OFF_BS2 = OFF_BR2 + 2u * 18432;  // 71680 (hi), +10240 (lo)
    // total smem = 71680 + 20480 = 92160

    extern __shared__ __align__(16) unsigned char dsm[];
    __shared__ int sidx[64];
    const uint32_t sbase = (uint32_t)__cvta_generic_to_shared(dsm);
    const int t = threadIdx.x, lane = t & 31, warp = t >> 5;
    const int wm = warp & 1, wn = warp >> 1;
    const int n0 = blockIdx.x * 128;
    const int kstart = blockIdx.y * KSPAN;
    const bool is_h = (MODE == 0) && (blockIdx.z == 1);
    const float* Wm = (MODE == 0) ? (is_h ? w1 : w0) : w0;

    if (MODE == 0 && !is_h && t < 64) sidx[t] = gidx[t];
    __syncthreads();

    // ---- preload A slice [64 x KSPAN] fp32 -> bf16 hi/lo planes ----
    {
        int row = t >> 2, seg = t & 3;
        const float* asrc;
        if (MODE == 0)
            asrc = is_h ? (lh + row * H + kstart)
                        : (emb + (size_t)sidx[row] * E + kstart);
        else
            asrc = (kstart < H) ? (g_hnew + row * H + kstart)
                                : (g_ctx  + row * H + kstart - H);
        unsigned char* ahw = dsm + row * ASTR;
        unsigned char* alw = dsm + APL + row * ASTR;
        #pragma unroll
        for (int q = 0; q < KSPAN / 16; q++) {            // 8 float4 per thread
            int c = seg * (KSPAN / 4) + q * 4;
            float4 v = *(const float4*)(asrc + c);
            unsigned h0, l0, h1, l1;
            split2(v.x, v.y, h0, l0);
            split2(v.z, v.w, h1, l1);
            *(uint2*)(ahw + c * 2) = make_uint2(h0, h1);
            *(uint2*)(alw + c * 2) = make_uint2(l0, l1);
        }
    }

    // ---- B loader precompute (128 rows x 32 fp32 per stage) ----
    uint32_t br_doff[4]; const float* br_src[4];
    #pragma unroll
    for (int j = 0; j < 4; j++) {
        int c = t + 256 * j;
        int row = c >> 3, seg = c & 7;
        br_doff[j] = OFF_BR2 + (uint32_t)(row * 144 + seg * 16);
        br_src[j] = Wm + (size_t)(n0 + row) * KTOT + kstart + seg * 4;
    }
    auto issue_stage = [&](int s) {
        #pragma unroll
        for (int j = 0; j < 4; j++)
            cp16(sbase + br_doff[j] + (uint32_t)(s & 1) * 18432u, br_src[j] + s * 32);
    };

    float acc[2][4][4];
    #pragma unroll
    for (int i = 0; i < 2; i++)
        #pragma unroll
        for (int j = 0; j < 4; j++)
            #pragma unroll
            for (int r = 0; r < 4; r++) acc[i][j][r] = 0.f;

    issue_stage(0); CP_COMMIT();
    issue_stage(1); CP_COMMIT();
    __syncthreads();   // A preload visible before compute

    const int cv_row = t >> 1, cv_half = t & 1;

    for (int s = 0; s < NST; s++) {
        CP_WAIT1();
        __syncthreads();
        // convert Br[s&1] fp32 -> Bs hi/lo bf16
        {
            const unsigned char* src = dsm + OFF_BR2 + (uint32_t)(s & 1) * 18432u
                                       + cv_row * 144 + cv_half * 64;
            const float4* s4 = (const float4*)src;
            uint4 ph[2], pl[2];
            #pragma unroll
            for (int hq = 0; hq < 2; hq++) {
                float4 va = s4[hq * 2], vb = s4[hq * 2 + 1];
                unsigned h0,l0,h1,l1,h2,l2,h3,l3;
                split2(va.x, va.y, h0, l0); split2(va.z, va.w, h1, l1);
                split2(vb.x, vb.y, h2, l2); split2(vb.z, vb.w, h3, l3);
                ph[hq] = make_uint4(h0, h1, h2, h3);
                pl[hq] = make_uint4(l0, l1, l2, l3);
            }
            uint4* dh = (uint4*)(dsm + OFF_BS2 + cv_row * 80 + cv_half * 32);
            uint4* dl = (uint4*)(dsm + OFF_BS2 + 10240 + cv_row * 80 + cv_half * 32);
            dh[0] = ph[0]; dh[1] = ph[1];
            dl[0] = pl[0]; dl[1] = pl[1];
        }
        __syncthreads();
        // compute: A cols s*32.. vs Bs (3-term hi/lo)
        #pragma unroll
        for (int ks = 0; ks < 2; ks++) {
            unsigned ah[2][4], al[2][4];
            #pragma unroll
            for (int tm = 0; tm < 2; tm++) {
                int row = wm * 32 + tm * 16 + ((lane >> 3) & 1) * 8 + (lane & 7);
                int col = s * 32 + ks * 16 + (lane >> 4) * 8;
                ldm_x4(ah[tm][0], ah[tm][1], ah[tm][2], ah[tm][3],
                       dsm + row * ASTR + col * 2);
                ldm_x4(al[tm][0], al[tm][1], al[tm][2], al[tm][3],
                       dsm + APL + row * ASTR + col * 2);
            }
            unsigned bh[4][2], bl[4][2];
            #pragma unroll
            for (int g = 0; g < 2; g++) {
                int nrow = wn * 32 + g * 16 + (lane >> 4) * 8 + (lane & 7);
                int col  = ks * 16 + ((lane >> 3) & 1) * 8;
                unsigned r0, r1, r2, r3;
                ldm_x4(r0, r1, r2, r3, dsm + OFF_BS2 + nrow * 80 + col * 2);
                bh[g*2+0][0] = r0; bh[g*2+0][1] = r1;
                bh[g*2+1][0] = r2; bh[g*2+1][1] = r3;
                ldm_x4(r0, r1, r2, r3, dsm + OFF_BS2 + 10240 + nrow * 80 + col * 2);
                bl[g*2+0][0] = r0; bl[g*2+0][1] = r1;
                bl[g*2+1][0] = r2; bl[g*2+1][1] = r3;
            }
            #pragma unroll
            for (int tm = 0; tm < 2; tm++)
                #pragma unroll
                for (int tn = 0; tn < 4; tn++) {
                    mma16816(acc[tm][tn], ah[tm], bh[tn][0], bh[tn][1]);
                    mma16816(acc[tm][tn], ah[tm], bl[tn][0], bl[tn][1]);
                    mma16816(acc[tm][tn], al[tm], bh[tn][0], bh[tn][1]);
                }
        }
        __syncthreads();
        if (s + 2 < NST) issue_stage(s + 2);
        CP_COMMIT();
    }

    // ---- epilogue: fp32 split-K partials [split][n][64b] ----
    float* outp = (MODE == 0) ? (is_h ? g_gh : g_gi) : g_cpart;
    const size_t base = (size_t)blockIdx.y * NTOT * 64;
    const int mrow  = wm * 32 + (lane >> 2);
    const int ncol0 = wn * 32 + 2 * (lane & 3);
    #pragma unroll
    for (int tm = 0; tm < 2; tm++) {
        #pragma unroll
        for (int tn = 0; tn < 4; tn++) {
            #pragma unroll
            for (int cc = 0; cc < 2; cc++) {
                int n = n0 + ncol0 + tn * 8 + cc;
                float* o = outp + base + (size_t)n * 64;
                o[mrow + tm * 16]     = acc[tm][tn][cc];
                o[mrow + tm * 16 + 8] = acc[tm][tn][2 + cc];
            }
        }
    }
}
constexpr uint32_t SMALL_SMEM = 92160;

// ---------------- GRU gates ----------------
__global__ void gru_gates(const float* __restrict__ lh, const float* __restrict__ b_ih,
                          const float* __restrict__ b_hh, float* __restrict__ dout)
{
    int idx = blockIdx.x * 256 + threadIdx.x;
    int j = idx >> 6, b = idx & 63;
    float ir = 0.f, iz = 0.f, inn = 0.f, hr = 0.f, hz = 0.f, hn = 0.f;
    #pragma unroll
    for (int s = 0; s < SPL; s++) {
        const float* gi = g_gi + (size_t)s * (3 * H * 64);
        const float* gh = g_gh + (size_t)s * (3 * H * 64);
        ir  += gi[j*64 + b];            hr  += gh[j*64 + b];
        iz  += gi[(H + j)*64 + b];      hz  += gh[(H + j)*64 + b];
        inn += gi[(2*H + j)*64 + b];    hn  += gh[(2*H + j)*64 + b];
    }
    ir += b_ih[j]; iz += b_ih[H + j]; inn += b_ih[2*H + j];
    hr += b_hh[j]; hz += b_hh[H + j]; hn  += b_hh[2*H + j];
    float r = 1.f / (1.f + expf(-(ir + hr)));
    float z = 1.f / (1.f + expf(-(iz + hz)));
    float n = tanhf(inn + r * hn);
    float h = lh[b * H + j];
    float hnew = (1.f - z) * n + z * h;
    g_hnew[b * H + j] = hnew;
    dout[BV + (size_t)b * H + j] = hnew;
}

// ---------------- attention: single-pass per (b, chunk) with online softmax ----------------
__global__ __launch_bounds__(256) void attn_fused(const float* __restrict__ enc)
{
    __shared__ __align__(16) float hn[H];
    __shared__ __align__(16) float4 sbuf[8][256];
    __shared__ float sm[8], sl[8];
    const int t = threadIdx.x, lane = t & 31, w = t >> 5;
    const int sp = blockIdx.x, b = blockIdx.y;

    ((float4*)hn)[t] = ((const float4*)(g_hnew + (size_t)b * H))[t];
    __syncthreads();
    const float4* hn4 = (const float4*)hn;

    float m = -1e30f, l = 0.f;
    float4 ctx[8];
    #pragma unroll
    for (int k = 0; k < 8; k++) ctx[k] = make_float4(0.f, 0.f, 0.f, 0.f);

    for (int i = 0; i < 8; i++) {
        int s = sp * 64 + w * 8 + i;
        const float4* e4 = (const float4*)(enc + ((size_t)b * SEQ + s) * H);
        float4 ev[8];
        float a = 0.f;
        #pragma unroll
        for (int k = 0; k < 8; k++) {
            ev[k] = e4[lane + 32 * k];
            float4 hv = hn4[lane + 32 * k];
            a += ev[k].x*hv.x + ev[k].y*hv.y + ev[k].z*hv.z + ev[k].w*hv.w;
        }
        #pragma unroll
        for (int o = 16; o > 0; o >>= 1) a += __shfl_xor_sync(0xffffffffu, a, o);
        if (a > m) {
            float sc = __expf(m - a);
            l *= sc;
            #pragma unroll
            for (int k = 0; k < 8; k++) {
                ctx[k].x *= sc; ctx[k].y *= sc; ctx[k].z *= sc; ctx[k].w *= sc;
            }
            m = a;
        }
        float p = __expf(a - m);
        l += p;
        #pragma unroll
        for (int k = 0; k < 8; k++) {
            ctx[k].x += p * ev[k].x; ctx[k].y += p * ev[k].y;
            ctx[k].z += p * ev[k].z; ctx[k].w += p * ev[k].w;
        }
    }

    if (lane == 0) { sm[w] = m; sl[w] = l; }
    __syncthreads();
    float M = -1e30f;
    #pragma unroll
    for (int w2 = 0; w2 < 8; w2++) M = fmaxf(M, sm[w2]);
    float e = __expf(m - M);
    #pragma unroll
    for (int k = 0; k < 8; k++) {
        float4 v = ctx[k];
        sbuf[w][lane + 32 * k] = make_float4(v.x * e, v.y * e, v.z * e, v.w * e);
    }
    float L = 0.f;
    #pragma unroll
    for (int w2 = 0; w2 < 8; w2++) L += sl[w2] * __expf(sm[w2] - M);
    __syncthreads();

    float4 acc = make_float4(0.f, 0.f, 0.f, 0.f);
    #pragma unroll
    for (int w2 = 0; w2 < 8; w2++) {
        float4 v = sbuf[w2][t];
        acc.x += v.x; acc.y += v.y; acc.z += v.z; acc.w += v.w;
    }
    *(float4*)(g_pctx + ((size_t)(b * 16 + sp)) * H + t * 4) = acc;
    if (t == 0) { g_pm[b * 16 + sp] = M; g_pl[b * 16 + sp] = L; }
}

// ---------------- attention combine: grid (4, 64), chunk-split + smem reduce ----------
__global__ __launch_bounds__(256) void attn_combine()
{
    __shared__ __align__(16) float4 red[4][64];
    const int b = blockIdx.y, t = threadIdx.x;
    const int grp = t >> 6;
    const int col = t & 63;
    const int j4 = (blockIdx.x * 64 + col) * 4;

    float M = -1e30f;
    #pragma unroll
    for (int c = 0; c < 16; c++) M = fmaxf(M, g_pm[b * 16 + c]);
    float L = 0.f;
    float e[4];
    #pragma unroll
    for (int c = 0; c < 16; c++) {
        float ec = __expf(g_pm[b * 16 + c] - M);
        L += g_pl[b * 16 + c] * ec;
        if ((c >> 2) == grp) e[c & 3] = ec;
    }
    float inv = 1.f / L;

    float4 acc = make_float4(0.f, 0.f, 0.f, 0.f);
    #pragma unroll
    for (int k = 0; k < 4; k++) {
        int c = grp * 4 + k;
        float4 v = *(const float4*)(g_pctx + ((size_t)(b * 16 + c)) * H + j4);
        float wv = e[k];
        acc.x += wv * v.x; acc.y += wv * v.y; acc.z += wv * v.z; acc.w += wv * v.w;
    }
    red[grp][col] = acc;
    __syncthreads();
    if (grp == 0) {
        #pragma unroll
        for (int g = 1; g < 4; g++) {
            float4 v = red[g][col];
            acc.x += v.x; acc.y += v.y; acc.z += v.z; acc.w += v.w;
        }
        *(float4*)(g_ctx + (size_t)b * H + j4) =
            make_float4(acc.x * inv, acc.y * inv, acc.z * inv, acc.w * inv);
    }
}

// ---------------- concat-gemm combine: bias + tanh -> bf16 A ----------------
__global__ void cat_combine(const float* __restrict__ cbias)
{
    int idx = blockIdx.x * 256 + threadIdx.x;
    int n = idx >> 6, b = idx & 63;
    float s = cbias[n];
    #pragma unroll
    for (int sp = 0; sp < CATSPL; sp++) s += g_cpart[((size_t)sp * H + n) * 64 + b];
    g_co_bf[b * H + n] = __float2bfloat16(tanhf(s));
}

// ---------------- output GEMM: direct-register fragments, no smem mainloop -------------
// Fragments loaded straight from global per canonical m16n8k16 layout:
//   A (bf16, g_co_bf, L2-hot):  r = wm*32+tm*16+lane/4 (+8), k = (lane&3)*2 (+8)
//   B (fp32 ow -> bf16 in regs): n = n0+wn*32+tn*8+lane/4,   k same
// 64 stages of k16; double-buffered register stages; zero barriers in the loop.
__global__ __launch_bounds__(256, 2) void out_gemm_dr(const float* __restrict__ ow,
                                                      const float* __restrict__ ob,
                                                      float* __restrict__ dout)
{
    __shared__ float sbias[NB];
    __shared__ float2 part[64 * 4];
    const int t = threadIdx.x, lane = t & 31, warp = t >> 5;
    const int n0 = blockIdx.x * NB;
    const int wm = warp & 1, wn = warp >> 1;     // warp tile: M32 x N32

    if (t < NB) {
        int n = n0 + t;
        sbias[t] = (n < V) ? ob[n] : 0.f;
    }

    const int qk = (lane & 3) * 2;     // k offset within k16 block
    const int qr = lane >> 2;          // fragment row/col group

    // A row pointers (rows r and r+8 per tm)
    const __nv_bfloat16* a_rp[2][2];
    #pragma unroll
    for (int tm = 0; tm < 2; tm++) {
        int r = wm * 32 + tm * 16 + qr;
        a_rp[tm][0] = g_co_bf + (size_t)r * H + qk;
        a_rp[tm][1] = g_co_bf + (size_t)(r + 8) * H + qk;
    }
    // B row pointers (one n per tn)
    const float* b_rp[4];
    #pragma unroll
    for (int tn = 0; tn < 4; tn++) {
        int n = n0 + wn * 32 + tn * 8 + qr;
        if (n >= V) n = V - 1;
        b_rp[tn] = ow + (size_t)n * 1024 + qk;
    }

    float2   bbuf[2][8];
    unsigned abuf[2][8];
    auto loadB = [&](int s, float2* bb) {
        const int k0 = s * 16;
        #pragma unroll
        for (int tn = 0; tn < 4; tn++) {
            bb[tn * 2 + 0] = *(const float2*)(b_rp[tn] + k0);
            bb[tn * 2 + 1] = *(const float2*)(b_rp[tn] + k0 + 8);
        }
    };
    auto loadA = [&](int s, unsigned* ab) {
        const int k0 = s * 16;
        #pragma unroll
        for (int tm = 0; tm < 2; tm++) {
            ab[tm * 4 + 0] = *(const unsigned*)(a_rp[tm][0] + k0);
            ab[tm * 4 + 1] = *(const unsigned*)(a_rp[tm][1] + k0);
            ab[tm * 4 + 2] = *(const unsigned*)(a_rp[tm][0] + k0 + 8);
            ab[tm * 4 + 3] = *(const unsigned*)(a_rp[tm][1] + k0 + 8);
        }
    };

    float acc[2][4][4];
    #pragma unroll
    for (int i = 0; i < 2; i++)
        #pragma unroll
        for (int j = 0; j < 4; j++)
            #pragma unroll
            for (int r = 0; r < 4; r++) acc[i][j][r] = 0.f;

    loadB(0, bbuf[0]);
    loadA(0, abuf[0]);

    #pragma unroll 2
    for (int s = 0; s < 64; s++) {
        const int cur = s & 1, nxt = cur ^ 1;
        if (s + 1 < 64) { loadB(s + 1, bbuf[nxt]); loadA(s + 1, abuf[nxt]); }
        unsigned bfr[8];
        #pragma unroll
        for (int i = 0; i < 8; i++) bfr[i] = pack_bf2(bbuf[cur][i].x, bbuf[cur][i].y);
        #pragma unroll
        for (int tm = 0; tm < 2; tm++)
            #pragma unroll
            for (int tn = 0; tn < 4; tn++)
                mma16816(acc[tm][tn], abuf[cur] + tm * 4, bfr[tn * 2], bfr[tn * 2 + 1]);
    }
    __syncthreads();   // sbias visible to all

    // epilogue: write logits + per-(row, block) online-softmax partials
    const int mrow  = wm * 32 + (lane >> 2);
    const int ncol0 = n0 + wn * 32 + 2 * (lane & 3);

    float pmv[4], plv[4];
    #pragma unroll
    for (int i = 0; i < 4; i++) { pmv[i] = -1e30f; plv[i] = 0.f; }

    #pragma unroll
    for (int tm = 0; tm < 2; tm++) {
        #pragma unroll
        for (int tn = 0; tn < 4; tn++) {
            int r = mrow + tm * 16;
            int c = ncol0 + tn * 8;
            #pragma unroll
            for (int cc = 0; cc < 2; cc++) {
                if (c + cc < V) {
                    float bb = sbias[c + cc - n0];
                    float v0 = acc[tm][tn][cc]     + bb;    // row r
                    float v1 = acc[tm][tn][2 + cc] + bb;    // row r+8
                    dout[(size_t)r * V + c + cc]       = v0;
                    dout[(size_t)(r + 8) * V + c + cc] = v1;
                    int i0 = 2 * tm, i1 = 2 * tm + 1;
                    if (v0 > pmv[i0]) { plv[i0] *= __expf(pmv[i0] - v0); pmv[i0] = v0; }
                    plv[i0] += __expf(v0 - pmv[i0]);
                    if (v1 > pmv[i1]) { plv[i1] *= __expf(pmv[i1] - v1); pmv[i1] = v1; }
                    plv[i1] += __expf(v1 - pmv[i1]);
                }
            }
        }
    }
    // reduce across the 4 lanes sharing each row
    #pragma unroll
    for (int i = 0; i < 4; i++) {
        #pragma unroll
        for (int off = 1; off <= 2; off <<= 1) {
            float om = __shfl_xor_sync(0xffffffffu, pmv[i], off);
            float ol = __shfl_xor_sync(0xffffffffu, plv[i], off);
            float nm = fmaxf(pmv[i], om);
            plv[i] = plv[i] * __expf(pmv[i] - nm) + ol * __expf(om - nm);
            pmv[i] = nm;
        }
    }
    if ((lane & 3) == 0) {
        #pragma unroll
        for (int i = 0; i < 4; i++) {
            int row = wm * 32 + (lane >> 2) + (i & 1) * 8 + (i >> 1) * 16;
            part[row * 4 + wn] = make_float2(pmv[i], plv[i]);
        }
    }
    __syncthreads();
    if (t < 64) {
        float m = -1e30f, l = 0.f;
        #pragma unroll
        for (int k = 0; k < 4; k++) {
            float2 p = part[t * 4 + k];
            float nm = fmaxf(m, p.x);
            l = l * __expf(m - nm) + p.y * __expf(p.x - nm);
            m = nm;
        }
        g_plse[t * NBLKP + blockIdx.x] = make_float2(m, l);
    }
}

// ---------------- final: reduce lse partials (redundantly per CTA) + subtract ----------
constexpr int SUBSPAN = 6288;   // 8 * 6288 >= V
__global__ __launch_bounds__(256) void sub_final(float* __restrict__ dout)
{
    __shared__ float rm[256], rl[256];
    const int b = blockIdx.y, cx = blockIdx.x, t = threadIdx.x;
    float m = -1e30f, l = 0.f;
    for (int i = t; i < NBLK; i += 256) {
        float2 p = g_plse[b * NBLKP + i];
        float nm = fmaxf(m, p.x);
        l = l * __expf(m - nm) + p.y * __expf(p.x - nm);
        m = nm;
    }
    rm[t] = m; rl[t] = l; __syncthreads();
    for (int o = 128; o > 0; o >>= 1) {
        if (t < o) {
            float m2 = fmaxf(rm[t], rm[t + o]);
            rl[t] = rl[t] * __expf(rm[t] - m2) + rl[t + o] * __expf(rm[t + o] - m2);
            rm[t] = m2;
        }
        __syncthreads();
    }
    float lse = rm[0] + logf(rl[0]);
    float* row = dout + (size_t)b * V;
    int end = cx * SUBSPAN + SUBSPAN; if (end > V) end = V;
    for (int v = cx * SUBSPAN + t; v < end; v += 256) row[v] -= lse;
}

// ---------------- launch ----------------
extern "C" void kernel_launch(void* const* d_in, const int* in_sizes, int n_in,
                              void* d_out, int out_size)
{
    const int*   seq = (const int*)  d_in[0];
    const float* lh  = (const float*)d_in[1];
    const float* enc = (const float*)d_in[2];
    const float* emb = (const float*)d_in[3];
    const float* wih = (const float*)d_in[4];
    const float* whh = (const float*)d_in[5];
    const float* bih = (const float*)d_in[6];
    const float* bhh = (const float*)d_in[7];
    const float* cw  = (const float*)d_in[8];
    const float* cb  = (const float*)d_in[9];
    const float* ow  = (const float*)d_in[10];
    const float* ob  = (const float*)d_in[11];
    float* dout = (float*)d_out;
    (void)in_sizes; (void)n_in; (void)out_size;

    static bool attr_done = false;
    if (!attr_done) {
        cudaFuncSetAttribute(mma_small<0, 3*H, H, SPL>,
                             cudaFuncAttributeMaxDynamicSharedMemorySize, SMALL_SMEM);
        cudaFuncSetAttribute(mma_small<2, H, 2*H, CATSPL>,
                             cudaFuncAttributeMaxDynamicSharedMemorySize, SMALL_SMEM);
        attr_done = true;
    }

    // GRU gate GEMMs on tensor cores, hi/lo bf16 (z=0: emb path, z=1: hidden path)
    mma_small<0, 3*H, H, SPL><<<dim3(24, SPL, 2), 256, SMALL_SMEM>>>(seq, emb, lh, wih, whh);
    gru_gates<<<256, 256>>>(lh, bih, bhh, dout);

    // attention (single HBM pass) + combine
    attn_fused<<<dim3(16, 64), 256>>>(enc);
    attn_combine<<<dim3(4, 64), 256>>>();

    // concat GEMM on tensor cores, hi/lo bf16 + tanh -> bf16
    mma_small<2, H, 2*H, CATSPL><<<dim3(8, CATSPL), 256, SMALL_SMEM>>>(nullptr, nullptr, nullptr, cw, nullptr);
    cat_combine<<<256, 256>>>(cb);

    // output GEMM (direct-register fragments) -> logits + lse partials
    out_gemm_dr<<<NBLK, 256>>>(ow, ob, dout);

    // reduce partials + subtract (full-chip)
    sub_final<<<dim3(8, 64), 256>>>(dout);
}

// round 14
// speedup vs baseline: 1.2887x; 1.2887x over previous
#include <cuda_runtime.h>
#include <cuda_bf16.h>
#include <math.h>
#include <stdint.h>

// Problem constants
constexpr int B  = 64;
constexpr int H  = 1024;
constexpr int E  = 1024;
constexpr int SEQ = 1024;
constexpr int V  = 50257;
constexpr long long BV = (long long)B * V;
constexpr int SPL = 8;                       // split-K for GRU gate GEMMs
constexpr int CATSPL = 16;                   // split-K for concat GEMM
constexpr int NB = 128;                      // out-gemm N tile
constexpr int NBLK  = (V + NB - 1) / NB;     // 393 col-blocks
constexpr int NBLKP = 400;                   // padded stride

// ---------------- scratch (static device memory; no allocs) ----------------
__device__ float g_gi[SPL * 3 * H * B];      // GRU input-gate partials  [split][row][b]
__device__ float g_gh[SPL * 3 * H * B];      // GRU hidden-gate partials
__device__ float g_hnew[B * H];              // new hidden state [b][h]
__device__ float g_pm[B * 16];               // attention chunk max
__device__ float g_pl[B * 16];               // attention chunk sum
__device__ float g_pctx[B * 16 * H];         // attention chunk context
__device__ float g_ctx[B * H];               // context [b][h]
__device__ float g_cpart[CATSPL * H * B];    // concat-gemm partials [split][n][b]
__device__ __nv_bfloat16 g_co_bf[B * H];     // concat_out (tanh) bf16 [b][n]
__device__ float2 g_plse[B * NBLKP];         // per-(row, colblock) softmax partials (m,l)
__device__ float g_lsev[B];                  // final lse per row
__device__ unsigned g_arrive;                // monotonic arrival counter (replay-safe)
__device__ unsigned g_done;                  // monotonic finalize counter

// ---------------- helpers ----------------
static __device__ __forceinline__ unsigned pack_bf2(float lo, float hi) {
    __nv_bfloat162 v = __floats2bfloat162_rn(lo, hi);
    return *reinterpret_cast<unsigned*>(&v);
}
// split fp32 pair into bf16 hi-plane word + bf16 residual word
static __device__ __forceinline__ void split2(float a, float b, unsigned& hi, unsigned& lo) {
    __nv_bfloat16 ha = __float2bfloat16(a), hb = __float2bfloat16(b);
    float ra = a - __bfloat162float(ha);
    float rb = b - __bfloat162float(hb);
    __nv_bfloat162 hv; hv.x = ha; hv.y = hb;
    hi = *reinterpret_cast<unsigned*>(&hv);
    lo = pack_bf2(ra, rb);
}
static __device__ __forceinline__ void ldm_x4(unsigned& r0, unsigned& r1,
                                              unsigned& r2, unsigned& r3, const void* p) {
    unsigned addr = (unsigned)__cvta_generic_to_shared(p);
    asm volatile("ldmatrix.sync.aligned.m8n8.x4.shared.b16 {%0,%1,%2,%3}, [%4];"
                 : "=r"(r0), "=r"(r1), "=r"(r2), "=r"(r3) : "r"(addr));
}
static __device__ __forceinline__ void mma16816(float* d, const unsigned* a,
                                                unsigned b0, unsigned b1) {
    asm volatile(
        "mma.sync.aligned.m16n8k16.row.col.f32.bf16.bf16.f32 "
        "{%0,%1,%2,%3}, {%4,%5,%6,%7}, {%8,%9}, {%0,%1,%2,%3};"
        : "+f"(d[0]), "+f"(d[1]), "+f"(d[2]), "+f"(d[3])
        : "r"(a[0]), "r"(a[1]), "r"(a[2]), "r"(a[3]), "r"(b0), "r"(b1));
}
static __device__ __forceinline__ void cp16(uint32_t dst_smem, const void* src) {
    asm volatile("cp.async.cg.shared.global [%0], [%1], 16;"
                 :: "r"(dst_smem), "l"(src) : "memory");
}
#define CP_COMMIT() asm volatile("cp.async.commit_group;" ::: "memory")
#define CP_WAIT1()  asm volatile("cp.async.wait_group 1;" ::: "memory")

// ---------------- small mma GEMMs with hi/lo bf16 (near-fp32 precision) ----------------
template<int MODE, int NTOT, int KTOT, int SPLITS>
__global__ __launch_bounds__(256) void mma_small(
    const int*   __restrict__ gidx,
    const float* __restrict__ emb,
    const float* __restrict__ lh,
    const float* __restrict__ w0,
    const float* __restrict__ w1)
{
    constexpr int KSPAN = KTOT / SPLITS;      // 128
    constexpr int NST   = KSPAN / 32;         // 4
    constexpr int ASTR  = KSPAN * 2 + 16;     // 272 B row stride per bf16 plane
    constexpr uint32_t APL    = 64u * ASTR;             // 17408 per A plane
    constexpr uint32_t OFF_BR2 = 2u * APL;              // 34816
    constexpr uint32_t OFF_BS2 = OFF_BR2 + 2u * 18432;  // 71680 (hi), +10240 (lo)

    extern __shared__ __align__(16) unsigned char dsm[];
    __shared__ int sidx[64];
    const uint32_t sbase = (uint32_t)__cvta_generic_to_shared(dsm);
    const int t = threadIdx.x, lane = t & 31, warp = t >> 5;
    const int wm = warp & 1, wn = warp >> 1;
    const int n0 = blockIdx.x * 128;
    const int kstart = blockIdx.y * KSPAN;
    const bool is_h = (MODE == 0) && (blockIdx.z == 1);
    const float* Wm = (MODE == 0) ? (is_h ? w1 : w0) : w0;

    if (MODE == 0 && !is_h && t < 64) sidx[t] = gidx[t];
    __syncthreads();

    // ---- preload A slice [64 x KSPAN] fp32 -> bf16 hi/lo planes ----
    {
        int row = t >> 2, seg = t & 3;
        const float* asrc;
        if (MODE == 0)
            asrc = is_h ? (lh + row * H + kstart)
                        : (emb + (size_t)sidx[row] * E + kstart);
        else
            asrc = (kstart < H) ? (g_hnew + row * H + kstart)
                                : (g_ctx  + row * H + kstart - H);
        unsigned char* ahw = dsm + row * ASTR;
        unsigned char* alw = dsm + APL + row * ASTR;
        #pragma unroll
        for (int q = 0; q < KSPAN / 16; q++) {
            int c = seg * (KSPAN / 4) + q * 4;
            float4 v = *(const float4*)(asrc + c);
            unsigned h0, l0, h1, l1;
            split2(v.x, v.y, h0, l0);
            split2(v.z, v.w, h1, l1);
            *(uint2*)(ahw + c * 2) = make_uint2(h0, h1);
            *(uint2*)(alw + c * 2) = make_uint2(l0, l1);
        }
    }

    uint32_t br_doff[4]; const float* br_src[4];
    #pragma unroll
    for (int j = 0; j < 4; j++) {
        int c = t + 256 * j;
        int row = c >> 3, seg = c & 7;
        br_doff[j] = OFF_BR2 + (uint32_t)(row * 144 + seg * 16);
        br_src[j] = Wm + (size_t)(n0 + row) * KTOT + kstart + seg * 4;
    }
    auto issue_stage = [&](int s) {
        #pragma unroll
        for (int j = 0; j < 4; j++)
            cp16(sbase + br_doff[j] + (uint32_t)(s & 1) * 18432u, br_src[j] + s * 32);
    };

    float acc[2][4][4];
    #pragma unroll
    for (int i = 0; i < 2; i++)
        #pragma unroll
        for (int j = 0; j < 4; j++)
            #pragma unroll
            for (int r = 0; r < 4; r++) acc[i][j][r] = 0.f;

    issue_stage(0); CP_COMMIT();
    issue_stage(1); CP_COMMIT();
    __syncthreads();

    const int cv_row = t >> 1, cv_half = t & 1;

    for (int s = 0; s < NST; s++) {
        CP_WAIT1();
        __syncthreads();
        {
            const unsigned char* src = dsm + OFF_BR2 + (uint32_t)(s & 1) * 18432u
                                       + cv_row * 144 + cv_half * 64;
            const float4* s4 = (const float4*)src;
            uint4 ph[2], pl[2];
            #pragma unroll
            for (int hq = 0; hq < 2; hq++) {
                float4 va = s4[hq * 2], vb = s4[hq * 2 + 1];
                unsigned h0,l0,h1,l1,h2,l2,h3,l3;
                split2(va.x, va.y, h0, l0); split2(va.z, va.w, h1, l1);
                split2(vb.x, vb.y, h2, l2); split2(vb.z, vb.w, h3, l3);
                ph[hq] = make_uint4(h0, h1, h2, h3);
                pl[hq] = make_uint4(l0, l1, l2, l3);
            }
            uint4* dh = (uint4*)(dsm + OFF_BS2 + cv_row * 80 + cv_half * 32);
            uint4* dl = (uint4*)(dsm + OFF_BS2 + 10240 + cv_row * 80 + cv_half * 32);
            dh[0] = ph[0]; dh[1] = ph[1];
            dl[0] = pl[0]; dl[1] = pl[1];
        }
        __syncthreads();
        #pragma unroll
        for (int ks = 0; ks < 2; ks++) {
            unsigned ah[2][4], al[2][4];
            #pragma unroll
            for (int tm = 0; tm < 2; tm++) {
                int row = wm * 32 + tm * 16 + ((lane >> 3) & 1) * 8 + (lane & 7);
                int col = s * 32 + ks * 16 + (lane >> 4) * 8;
                ldm_x4(ah[tm][0], ah[tm][1], ah[tm][2], ah[tm][3],
                       dsm + row * ASTR + col * 2);
                ldm_x4(al[tm][0], al[tm][1], al[tm][2], al[tm][3],
                       dsm + APL + row * ASTR + col * 2);
            }
            unsigned bh[4][2], bl[4][2];
            #pragma unroll
            for (int g = 0; g < 2; g++) {
                int nrow = wn * 32 + g * 16 + (lane >> 4) * 8 + (lane & 7);
                int col  = ks * 16 + ((lane >> 3) & 1) * 8;
                unsigned r0, r1, r2, r3;
                ldm_x4(r0, r1, r2, r3, dsm + OFF_BS2 + nrow * 80 + col * 2);
                bh[g*2+0][0] = r0; bh[g*2+0][1] = r1;
                bh[g*2+1][0] = r2; bh[g*2+1][1] = r3;
                ldm_x4(r0, r1, r2, r3, dsm + OFF_BS2 + 10240 + nrow * 80 + col * 2);
                bl[g*2+0][0] = r0; bl[g*2+0][1] = r1;
                bl[g*2+1][0] = r2; bl[g*2+1][1] = r3;
            }
            #pragma unroll
            for (int tm = 0; tm < 2; tm++)
                #pragma unroll
                for (int tn = 0; tn < 4; tn++) {
                    mma16816(acc[tm][tn], ah[tm], bh[tn][0], bh[tn][1]);
                    mma16816(acc[tm][tn], ah[tm], bl[tn][0], bl[tn][1]);
                    mma16816(acc[tm][tn], al[tm], bh[tn][0], bh[tn][1]);
                }
        }
        __syncthreads();
        if (s + 2 < NST) issue_stage(s + 2);
        CP_COMMIT();
    }

    float* outp = (MODE == 0) ? (is_h ? g_gh : g_gi) : g_cpart;
    const size_t base = (size_t)blockIdx.y * NTOT * 64;
    const int mrow  = wm * 32 + (lane >> 2);
    const int ncol0 = wn * 32 + 2 * (lane & 3);
    #pragma unroll
    for (int tm = 0; tm < 2; tm++) {
        #pragma unroll
        for (int tn = 0; tn < 4; tn++) {
            #pragma unroll
            for (int cc = 0; cc < 2; cc++) {
                int n = n0 + ncol0 + tn * 8 + cc;
                float* o = outp + base + (size_t)n * 64;
                o[mrow + tm * 16]     = acc[tm][tn][cc];
                o[mrow + tm * 16 + 8] = acc[tm][tn][2 + cc];
            }
        }
    }
}
constexpr uint32_t SMALL_SMEM = 92160;

// ---------------- GRU gates ----------------
__global__ void gru_gates(const float* __restrict__ lh, const float* __restrict__ b_ih,
                          const float* __restrict__ b_hh, float* __restrict__ dout)
{
    int idx = blockIdx.x * 256 + threadIdx.x;
    int j = idx >> 6, b = idx & 63;
    float ir = 0.f, iz = 0.f, inn = 0.f, hr = 0.f, hz = 0.f, hn = 0.f;
    #pragma unroll
    for (int s = 0; s < SPL; s++) {
        const float* gi = g_gi + (size_t)s * (3 * H * 64);
        const float* gh = g_gh + (size_t)s * (3 * H * 64);
        ir  += gi[j*64 + b];            hr  += gh[j*64 + b];
        iz  += gi[(H + j)*64 + b];      hz  += gh[(H + j)*64 + b];
        inn += gi[(2*H + j)*64 + b];    hn  += gh[(2*H + j)*64 + b];
    }
    ir += b_ih[j]; iz += b_ih[H + j]; inn += b_ih[2*H + j];
    hr += b_hh[j]; hz += b_hh[H + j]; hn  += b_hh[2*H + j];
    float r = 1.f / (1.f + expf(-(ir + hr)));
    float z = 1.f / (1.f + expf(-(iz + hz)));
    float n = tanhf(inn + r * hn);
    float h = lh[b * H + j];
    float hnew = (1.f - z) * n + z * h;
    g_hnew[b * H + j] = hnew;
    dout[BV + (size_t)b * H + j] = hnew;
}

// ---------------- attention: single-pass per (b, chunk) with online softmax ----------------
__global__ __launch_bounds__(256) void attn_fused(const float* __restrict__ enc)
{
    __shared__ __align__(16) float hn[H];
    __shared__ __align__(16) float4 sbuf[8][256];
    __shared__ float sm[8], sl[8];
    const int t = threadIdx.x, lane = t & 31, w = t >> 5;
    const int sp = blockIdx.x, b = blockIdx.y;

    ((float4*)hn)[t] = ((const float4*)(g_hnew + (size_t)b * H))[t];
    __syncthreads();
    const float4* hn4 = (const float4*)hn;

    float m = -1e30f, l = 0.f;
    float4 ctx[8];
    #pragma unroll
    for (int k = 0; k < 8; k++) ctx[k] = make_float4(0.f, 0.f, 0.f, 0.f);

    for (int i = 0; i < 8; i++) {
        int s = sp * 64 + w * 8 + i;
        const float4* e4 = (const float4*)(enc + ((size_t)b * SEQ + s) * H);
        float4 ev[8];
        float a = 0.f;
        #pragma unroll
        for (int k = 0; k < 8; k++) {
            ev[k] = e4[lane + 32 * k];
            float4 hv = hn4[lane + 32 * k];
            a += ev[k].x*hv.x + ev[k].y*hv.y + ev[k].z*hv.z + ev[k].w*hv.w;
        }
        #pragma unroll
        for (int o = 16; o > 0; o >>= 1) a += __shfl_xor_sync(0xffffffffu, a, o);
        if (a > m) {
            float sc = __expf(m - a);
            l *= sc;
            #pragma unroll
            for (int k = 0; k < 8; k++) {
                ctx[k].x *= sc; ctx[k].y *= sc; ctx[k].z *= sc; ctx[k].w *= sc;
            }
            m = a;
        }
        float p = __expf(a - m);
        l += p;
        #pragma unroll
        for (int k = 0; k < 8; k++) {
            ctx[k].x += p * ev[k].x; ctx[k].y += p * ev[k].y;
            ctx[k].z += p * ev[k].z; ctx[k].w += p * ev[k].w;
        }
    }

    if (lane == 0) { sm[w] = m; sl[w] = l; }
    __syncthreads();
    float M = -1e30f;
    #pragma unroll
    for (int w2 = 0; w2 < 8; w2++) M = fmaxf(M, sm[w2]);
    float e = __expf(m - M);
    #pragma unroll
    for (int k = 0; k < 8; k++) {
        float4 v = ctx[k];
        sbuf[w][lane + 32 * k] = make_float4(v.x * e, v.y * e, v.z * e, v.w * e);
    }
    float L = 0.f;
    #pragma unroll
    for (int w2 = 0; w2 < 8; w2++) L += sl[w2] * __expf(sm[w2] - M);
    __syncthreads();

    float4 acc = make_float4(0.f, 0.f, 0.f, 0.f);
    #pragma unroll
    for (int w2 = 0; w2 < 8; w2++) {
        float4 v = sbuf[w2][t];
        acc.x += v.x; acc.y += v.y; acc.z += v.z; acc.w += v.w;
    }
    *(float4*)(g_pctx + ((size_t)(b * 16 + sp)) * H + t * 4) = acc;
    if (t == 0) { g_pm[b * 16 + sp] = M; g_pl[b * 16 + sp] = L; }
}

// ---------------- attention combine: grid (4, 64), chunk-split + smem reduce ----------
__global__ __launch_bounds__(256) void attn_combine()
{
    __shared__ __align__(16) float4 red[4][64];
    const int b = blockIdx.y, t = threadIdx.x;
    const int grp = t >> 6;
    const int col = t & 63;
    const int j4 = (blockIdx.x * 64 + col) * 4;

    float M = -1e30f;
    #pragma unroll
    for (int c = 0; c < 16; c++) M = fmaxf(M, g_pm[b * 16 + c]);
    float L = 0.f;
    float e[4];
    #pragma unroll
    for (int c = 0; c < 16; c++) {
        float ec = __expf(g_pm[b * 16 + c] - M);
        L += g_pl[b * 16 + c] * ec;
        if ((c >> 2) == grp) e[c & 3] = ec;
    }
    float inv = 1.f / L;

    float4 acc = make_float4(0.f, 0.f, 0.f, 0.f);
    #pragma unroll
    for (int k = 0; k < 4; k++) {
        int c = grp * 4 + k;
        float4 v = *(const float4*)(g_pctx + ((size_t)(b * 16 + c)) * H + j4);
        float wv = e[k];
        acc.x += wv * v.x; acc.y += wv * v.y; acc.z += wv * v.z; acc.w += wv * v.w;
    }
    red[grp][col] = acc;
    __syncthreads();
    if (grp == 0) {
        #pragma unroll
        for (int g = 1; g < 4; g++) {
            float4 v = red[g][col];
            acc.x += v.x; acc.y += v.y; acc.z += v.z; acc.w += v.w;
        }
        *(float4*)(g_ctx + (size_t)b * H + j4) =
            make_float4(acc.x * inv, acc.y * inv, acc.z * inv, acc.w * inv);
    }
}

// ---------------- concat-gemm combine: bias + tanh -> bf16 A ----------------
__global__ void cat_combine(const float* __restrict__ cbias)
{
    int idx = blockIdx.x * 256 + threadIdx.x;
    int n = idx >> 6, b = idx & 63;
    float s = cbias[n];
    #pragma unroll
    for (int sp = 0; sp < CATSPL; sp++) s += g_cpart[((size_t)sp * H + n) * 64 + b];
    g_co_bf[b * H + n] = __float2bfloat16(tanhf(s));
}

// ---------------- output GEMM: 3-deep cp.async ring + GRID-WIDE log-softmax finalize ---
// All 393 CTAs are co-resident (3 CTA/SM enforced, 393 < 444). After the mainloop each
// CTA deposits per-row (m,l) partials, arrives on a monotonic counter (epoch=arr/NBLK,
// replay-safe), CTA that arrives as blockIdx 0 reduces to g_lsev[64], bumps g_done;
// everyone spins, then writes acc+bias-lse ONCE. Removes sub_final + 25.6MB of traffic.
constexpr int KC = 32;
constexpr int NST32 = H / KC;                 // 32 stages
constexpr uint32_t OFF_AS = 0;
constexpr uint32_t OFF_BS = 5120;
constexpr uint32_t OFF_BR = 15360;
constexpr uint32_t BR_STG = 18432;
constexpr uint32_t OFF_BIAS = 70656;
constexpr uint32_t OUT_SMEM = 71168;

__global__ __launch_bounds__(256, 3) void out_gemm_cp(const float* __restrict__ ow,
                                                      const float* __restrict__ ob,
                                                      float* __restrict__ dout)
{
    extern __shared__ __align__(16) unsigned char dsm[];
    const uint32_t sbase = (uint32_t)__cvta_generic_to_shared(dsm);
    const int t = threadIdx.x, lane = t & 31, warp = t >> 5;
    const int n0 = blockIdx.x * NB;
    const int wm = warp & 1, wn = warp >> 1;     // warp tile: M32 x N32

    if (t < NB) {
        int n = n0 + t;
        ((float*)(dsm + OFF_BIAS))[t] = (n < V) ? ob[n] : 0.f;
    }

    // A loader (plain LDG, L2-resident; 1 stage ahead in regs)
    const int a_row = t >> 2, a_seg = t & 3;
    const uint32_t a_sts = OFF_AS + (uint32_t)(a_row * 80 + a_seg * 16);
    const __nv_bfloat16* a_src = g_co_bf + a_row * H + a_seg * 8;
    // B raw loader (cp.async, 3-buffer ring)
    uint32_t br_doff[4]; const float* br_src[4];
    #pragma unroll
    for (int j = 0; j < 4; j++) {
        int c = t + 256 * j;
        int row = c >> 3, seg = c & 7;
        br_doff[j] = OFF_BR + (uint32_t)(row * 144 + seg * 16);
        int gr = n0 + row; if (gr >= V) gr = V - 1;
        br_src[j] = ow + (size_t)gr * 1024 + seg * 4;
    }
    auto issueB = [&](int s) {
        const uint32_t stg = (uint32_t)(s % 3);
        #pragma unroll
        for (int j = 0; j < 4; j++)
            cp16(sbase + br_doff[j] + stg * BR_STG, br_src[j] + s * KC);
    };

    float acc[2][4][4];
    #pragma unroll
    for (int i = 0; i < 2; i++)
        #pragma unroll
        for (int j = 0; j < 4; j++)
            #pragma unroll
            for (int r = 0; r < 4; r++) acc[i][j][r] = 0.f;

    uint4 aregs = *(const uint4*)(a_src);
    issueB(0); CP_COMMIT();
    issueB(1); CP_COMMIT();

    const int cv_row = t >> 1, cv_half = t & 1;

    for (int s = 0; s < NST32; s++) {
        CP_WAIT1();
        __syncthreads();

        *(uint4*)(dsm + a_sts) = aregs;
        {
            const unsigned char* src = dsm + OFF_BR + (uint32_t)(s % 3) * BR_STG
                                       + cv_row * 144 + cv_half * 64;
            const float4* s4 = (const float4*)src;
            float4 v0 = s4[0], v1 = s4[1], v2 = s4[2], v3 = s4[3];
            uint4 p0 = make_uint4(pack_bf2(v0.x, v0.y), pack_bf2(v0.z, v0.w),
                                  pack_bf2(v1.x, v1.y), pack_bf2(v1.z, v1.w));
            uint4 p1 = make_uint4(pack_bf2(v2.x, v2.y), pack_bf2(v2.z, v2.w),
                                  pack_bf2(v3.x, v3.y), pack_bf2(v3.z, v3.w));
            uint4* dst = (uint4*)(dsm + OFF_BS + cv_row * 80 + cv_half * 32);
            dst[0] = p0; dst[1] = p1;
        }
        if (s + 2 < NST32) issueB(s + 2);
        CP_COMMIT();
        {
            int kA = (s + 1 < NST32) ? (s + 1) * KC : 0;
            aregs = *(const uint4*)(a_src + kA);
        }
        __syncthreads();

        #pragma unroll
        for (int ks = 0; ks < 2; ks++) {
            unsigned afr[2][4];
            #pragma unroll
            for (int tm = 0; tm < 2; tm++) {
                int row = wm * 32 + tm * 16 + ((lane >> 3) & 1) * 8 + (lane & 7);
                int col = ks * 16 + (lane >> 4) * 8;
                ldm_x4(afr[tm][0], afr[tm][1], afr[tm][2], afr[tm][3],
                       dsm + OFF_AS + row * 80 + col * 2);
            }
            unsigned bfr[4][2];
            #pragma unroll
            for (int g = 0; g < 2; g++) {
                int nrow = wn * 32 + g * 16 + (lane >> 4) * 8 + (lane & 7);
                int col  = ks * 16 + ((lane >> 3) & 1) * 8;
                unsigned r0, r1, r2, r3;
                ldm_x4(r0, r1, r2, r3, dsm + OFF_BS + nrow * 80 + col * 2);
                bfr[g*2+0][0] = r0; bfr[g*2+0][1] = r1;
                bfr[g*2+1][0] = r2; bfr[g*2+1][1] = r3;
            }
            #pragma unroll
            for (int tm = 0; tm < 2; tm++)
                #pragma unroll
                for (int tn = 0; tn < 4; tn++)
                    mma16816(acc[tm][tn], afr[tm], bfr[tn][0], bfr[tn][1]);
        }
    }
    __syncthreads();    // protect As-region reuse below

    // ---- per-(row, block) online-softmax partials (logits stay in registers) ----
    const float* sbias = (const float*)(dsm + OFF_BIAS);
    float2* part = (float2*)dsm;                 // reuse As region (2KB)
    __shared__ unsigned s_epoch;
    const int mrow  = wm * 32 + (lane >> 2);
    const int ncol0 = n0 + wn * 32 + 2 * (lane & 3);

    float pmv[4], plv[4];
    #pragma unroll
    for (int i = 0; i < 4; i++) { pmv[i] = -1e30f; plv[i] = 0.f; }

    #pragma unroll
    for (int tm = 0; tm < 2; tm++) {
        #pragma unroll
        for (int tn = 0; tn < 4; tn++) {
            int r0i = 2 * tm, r1i = 2 * tm + 1;
            int c = ncol0 + tn * 8;
            #pragma unroll
            for (int cc = 0; cc < 2; cc++) {
                if (c + cc < V) {
                    float bb = sbias[c + cc - n0];
                    float v0 = acc[tm][tn][cc]     + bb;
                    float v1 = acc[tm][tn][2 + cc] + bb;
                    if (v0 > pmv[r0i]) { plv[r0i] *= __expf(pmv[r0i] - v0); pmv[r0i] = v0; }
                    plv[r0i] += __expf(v0 - pmv[r0i]);
                    if (v1 > pmv[r1i]) { plv[r1i] *= __expf(pmv[r1i] - v1); pmv[r1i] = v1; }
                    plv[r1i] += __expf(v1 - pmv[r1i]);
                }
            }
        }
    }
    #pragma unroll
    for (int i = 0; i < 4; i++) {
        #pragma unroll
        for (int off = 1; off <= 2; off <<= 1) {
            float om = __shfl_xor_sync(0xffffffffu, pmv[i], off);
            float ol = __shfl_xor_sync(0xffffffffu, plv[i], off);
            float nm = fmaxf(pmv[i], om);
            plv[i] = plv[i] * __expf(pmv[i] - nm) + ol * __expf(om - nm);
            pmv[i] = nm;
        }
    }
    if ((lane & 3) == 0) {
        #pragma unroll
        for (int i = 0; i < 4; i++) {
            int row = wm * 32 + (lane >> 2) + (i & 1) * 8 + (i >> 1) * 16;
            part[row * 4 + wn] = make_float2(pmv[i], plv[i]);
        }
    }
    __syncthreads();
    if (t < 64) {
        float m = -1e30f, l = 0.f;
        #pragma unroll
        for (int k = 0; k < 4; k++) {
            float2 p = part[t * 4 + k];
            float nm = fmaxf(m, p.x);
            l = l * __expf(m - nm) + p.y * __expf(p.x - nm);
            m = nm;
        }
        g_plse[t * NBLKP + blockIdx.x] = make_float2(m, l);
    }
    __syncthreads();

    // ---- grid-wide arrive (monotonic, replay-safe) ----
    if (t == 0) {
        __threadfence();
        unsigned arr = atomicAdd(&g_arrive, 1u);
        unsigned epoch = arr / (unsigned)NBLK;
        s_epoch = epoch;
        unsigned target = (epoch + 1u) * (unsigned)NBLK;
        volatile unsigned* va = &g_arrive;
        while (*va < target) __nanosleep(64);
        __threadfence();
    }
    __syncthreads();
    const unsigned epoch = s_epoch;

    // ---- finalizer: blockIdx 0 reduces 393 partials per row -> g_lsev ----
    if (blockIdx.x == 0) {
        if (t < 64) {
            float m = -1e30f, l = 0.f;
            for (int i = 0; i < NBLK; i++) {
                float2 p = g_plse[t * NBLKP + i];
                float nm = fmaxf(m, p.x);
                l = l * __expf(m - nm) + p.y * __expf(p.x - nm);
                m = nm;
            }
            g_lsev[t] = m + logf(l);
        }
        __syncthreads();
        if (t == 0) {
            __threadfence();
            atomicAdd(&g_done, 1u);
        }
    }
    if (t == 0) {
        volatile unsigned* vd = &g_done;
        while (*vd < epoch + 1u) __nanosleep(64);
        __threadfence();
    }
    __syncthreads();

    // ---- final write: logits - lse, single pass ----
    float lse[4];
    {
        volatile const float* lv = g_lsev;
        #pragma unroll
        for (int tm = 0; tm < 2; tm++) {
            lse[2*tm]     = lv[mrow + tm * 16];
            lse[2*tm + 1] = lv[mrow + tm * 16 + 8];
        }
    }
    #pragma unroll
    for (int tm = 0; tm < 2; tm++) {
        #pragma unroll
        for (int tn = 0; tn < 4; tn++) {
            int r = mrow + tm * 16;
            int c = ncol0 + tn * 8;
            #pragma unroll
            for (int cc = 0; cc < 2; cc++) {
                if (c + cc < V) {
                    float bb = sbias[c + cc - n0];
                    dout[(size_t)r * V + c + cc]       = acc[tm][tn][cc]     + bb - lse[2*tm];
                    dout[(size_t)(r + 8) * V + c + cc] = acc[tm][tn][2 + cc] + bb - lse[2*tm+1];
                }
            }
        }
    }
}

// ---------------- launch ----------------
extern "C" void kernel_launch(void* const* d_in, const int* in_sizes, int n_in,
                              void* d_out, int out_size)
{
    const int*   seq = (const int*)  d_in[0];
    const float* lh  = (const float*)d_in[1];
    const float* enc = (const float*)d_in[2];
    const float* emb = (const float*)d_in[3];
    const float* wih = (const float*)d_in[4];
    const float* whh = (const float*)d_in[5];
    const float* bih = (const float*)d_in[6];
    const float* bhh = (const float*)d_in[7];
    const float* cw  = (const float*)d_in[8];
    const float* cb  = (const float*)d_in[9];
    const float* ow  = (const float*)d_in[10];
    const float* ob  = (const float*)d_in[11];
    float* dout = (float*)d_out;
    (void)in_sizes; (void)n_in; (void)out_size;

    static bool attr_done = false;
    if (!attr_done) {
        cudaFuncSetAttribute(out_gemm_cp,
                             cudaFuncAttributeMaxDynamicSharedMemorySize, OUT_SMEM);
        cudaFuncSetAttribute(mma_small<0, 3*H, H, SPL>,
                             cudaFuncAttributeMaxDynamicSharedMemorySize, SMALL_SMEM);
        cudaFuncSetAttribute(mma_small<2, H, 2*H, CATSPL>,
                             cudaFuncAttributeMaxDynamicSharedMemorySize, SMALL_SMEM);
        attr_done = true;
    }

    // GRU gate GEMMs on tensor cores, hi/lo bf16 (z=0: emb path, z=1: hidden path)
    mma_small<0, 3*H, H, SPL><<<dim3(24, SPL, 2), 256, SMALL_SMEM>>>(seq, emb, lh, wih, whh);
    gru_gates<<<256, 256>>>(lh, bih, bhh, dout);

    // attention (single HBM pass) + combine
    attn_fused<<<dim3(16, 64), 256>>>(enc);
    attn_combine<<<dim3(4, 64), 256>>>();

    // concat GEMM on tensor cores, hi/lo bf16 + tanh -> bf16
    mma_small<2, H, 2*H, CATSPL><<<dim3(8, CATSPL), 256, SMALL_SMEM>>>(nullptr, nullptr, nullptr, cw, nullptr);
    cat_combine<<<256, 256>>>(cb);

    // output GEMM + grid-wide fused log-softmax (single wave, co-resident)
    out_gemm_cp<<<NBLK, 256, OUT_SMEM>>>(ow, ob, dout);
}

// round 15
// speedup vs baseline: 1.6409x; 1.2733x over previous
#include <cuda_runtime.h>
#include <cuda_bf16.h>
#include <math.h>
#include <stdint.h>

// Problem constants
constexpr int B  = 64;
constexpr int H  = 1024;
constexpr int E  = 1024;
constexpr int SEQ = 1024;
constexpr int V  = 50257;
constexpr long long BV = (long long)B * V;
constexpr int SPL = 8;                       // split-K for GRU gate GEMMs
constexpr int CATSPL = 16;                   // split-K for concat GEMM
constexpr int NB = 128;                      // out-gemm N tile
constexpr int NBLK  = (V + NB - 1) / NB;     // 393 col-blocks
constexpr int NBLKP = 400;                   // padded stride

// ---------------- scratch (static device memory; no allocs) ----------------
__device__ float g_gi[SPL * 3 * H * B];      // GRU input-gate partials  [split][row][b]
__device__ float g_gh[SPL * 3 * H * B];      // GRU hidden-gate partials
__device__ float g_hnew[B * H];              // new hidden state [b][h]
__device__ float g_pm[B * 16];               // attention chunk max
__device__ float g_pl[B * 16];               // attention chunk sum
__device__ float g_pctx[B * 16 * H];         // attention chunk context
__device__ float g_ctx[B * H];               // context [b][h]
__device__ float g_cpart[CATSPL * H * B];    // concat-gemm partials [split][n][b]
__device__ __nv_bfloat16 g_co_bf[B * H];     // concat_out (tanh) bf16 [b][n]
__device__ float2 g_plse[B * NBLKP];         // per-(row, colblock) softmax partials (m,l)

// ---------------- helpers ----------------
static __device__ __forceinline__ unsigned pack_bf2(float lo, float hi) {
    __nv_bfloat162 v = __floats2bfloat162_rn(lo, hi);
    return *reinterpret_cast<unsigned*>(&v);
}
// split fp32 pair into bf16 hi-plane word + bf16 residual word
static __device__ __forceinline__ void split2(float a, float b, unsigned& hi, unsigned& lo) {
    __nv_bfloat16 ha = __float2bfloat16(a), hb = __float2bfloat16(b);
    float ra = a - __bfloat162float(ha);
    float rb = b - __bfloat162float(hb);
    __nv_bfloat162 hv; hv.x = ha; hv.y = hb;
    hi = *reinterpret_cast<unsigned*>(&hv);
    lo = pack_bf2(ra, rb);
}
static __device__ __forceinline__ void ldm_x4(unsigned& r0, unsigned& r1,
                                              unsigned& r2, unsigned& r3, const void* p) {
    unsigned addr = (unsigned)__cvta_generic_to_shared(p);
    asm volatile("ldmatrix.sync.aligned.m8n8.x4.shared.b16 {%0,%1,%2,%3}, [%4];"
                 : "=r"(r0), "=r"(r1), "=r"(r2), "=r"(r3) : "r"(addr));
}
static __device__ __forceinline__ void mma16816(float* d, const unsigned* a,
                                                unsigned b0, unsigned b1) {
    asm volatile(
        "mma.sync.aligned.m16n8k16.row.col.f32.bf16.bf16.f32 "
        "{%0,%1,%2,%3}, {%4,%5,%6,%7}, {%8,%9}, {%0,%1,%2,%3};"
        : "+f"(d[0]), "+f"(d[1]), "+f"(d[2]), "+f"(d[3])
        : "r"(a[0]), "r"(a[1]), "r"(a[2]), "r"(a[3]), "r"(b0), "r"(b1));
}
static __device__ __forceinline__ void cp16(uint32_t dst_smem, const void* src) {
    asm volatile("cp.async.cg.shared.global [%0], [%1], 16;"
                 :: "r"(dst_smem), "l"(src) : "memory");
}
#define CP_COMMIT() asm volatile("cp.async.commit_group;" ::: "memory")
#define CP_WAIT1()  asm volatile("cp.async.wait_group 1;" ::: "memory")

// ---------------- small mma GEMMs with hi/lo bf16 (near-fp32 precision) ----------------
// C[64 x NTOT] = A[64 x KTOT] @ W[NTOT x KTOT]^T, split-K partials [split][n][64b].
// MODE 0: GRU pair (z=0: gi/emb-gather, z=1: gh/last_hidden).  MODE 2: concat GEMM.
// acc += Ahi@Bhi + Ahi@Blo + Alo@Bhi  (lo*lo dropped, ~2^-16 rel)
template<int MODE, int NTOT, int KTOT, int SPLITS>
__global__ __launch_bounds__(256) void mma_small(
    const int*   __restrict__ gidx,
    const float* __restrict__ emb,
    const float* __restrict__ lh,
    const float* __restrict__ w0,
    const float* __restrict__ w1)
{
    constexpr int KSPAN = KTOT / SPLITS;      // 128
    constexpr int NST   = KSPAN / 32;         // 4
    constexpr int ASTR  = KSPAN * 2 + 16;     // 272 B row stride per bf16 plane
    constexpr uint32_t APL    = 64u * ASTR;             // 17408 per A plane
    constexpr uint32_t OFF_BR2 = 2u * APL;              // 34816
    constexpr uint32_t OFF_BS2 = OFF_BR2 + 2u * 18432;  // 71680 (hi), +10240 (lo)
    // total smem = 71680 + 20480 = 92160

    extern __shared__ __align__(16) unsigned char dsm[];
    __shared__ int sidx[64];
    const uint32_t sbase = (uint32_t)__cvta_generic_to_shared(dsm);
    const int t = threadIdx.x, lane = t & 31, warp = t >> 5;
    const int wm = warp & 1, wn = warp >> 1;
    const int n0 = blockIdx.x * 128;
    const int kstart = blockIdx.y * KSPAN;
    const bool is_h = (MODE == 0) && (blockIdx.z == 1);
    const float* Wm = (MODE == 0) ? (is_h ? w1 : w0) : w0;

    if (MODE == 0 && !is_h && t < 64) sidx[t] = gidx[t];
    __syncthreads();

    // ---- preload A slice [64 x KSPAN] fp32 -> bf16 hi/lo planes ----
    {
        int row = t >> 2, seg = t & 3;
        const float* asrc;
        if (MODE == 0)
            asrc = is_h ? (lh + row * H + kstart)
                        : (emb + (size_t)sidx[row] * E + kstart);
        else
            asrc = (kstart < H) ? (g_hnew + row * H + kstart)
                                : (g_ctx  + row * H + kstart - H);
        unsigned char* ahw = dsm + row * ASTR;
        unsigned char* alw = dsm + APL + row * ASTR;
        #pragma unroll
        for (int q = 0; q < KSPAN / 16; q++) {            // 8 float4 per thread
            int c = seg * (KSPAN / 4) + q * 4;
            float4 v = *(const float4*)(asrc + c);
            unsigned h0, l0, h1, l1;
            split2(v.x, v.y, h0, l0);
            split2(v.z, v.w, h1, l1);
            *(uint2*)(ahw + c * 2) = make_uint2(h0, h1);
            *(uint2*)(alw + c * 2) = make_uint2(l0, l1);
        }
    }

    // ---- B loader precompute (128 rows x 32 fp32 per stage) ----
    uint32_t br_doff[4]; const float* br_src[4];
    #pragma unroll
    for (int j = 0; j < 4; j++) {
        int c = t + 256 * j;
        int row = c >> 3, seg = c & 7;
        br_doff[j] = OFF_BR2 + (uint32_t)(row * 144 + seg * 16);
        br_src[j] = Wm + (size_t)(n0 + row) * KTOT + kstart + seg * 4;
    }
    auto issue_stage = [&](int s) {
        #pragma unroll
        for (int j = 0; j < 4; j++)
            cp16(sbase + br_doff[j] + (uint32_t)(s & 1) * 18432u, br_src[j] + s * 32);
    };

    float acc[2][4][4];
    #pragma unroll
    for (int i = 0; i < 2; i++)
        #pragma unroll
        for (int j = 0; j < 4; j++)
            #pragma unroll
            for (int r = 0; r < 4; r++) acc[i][j][r] = 0.f;

    issue_stage(0); CP_COMMIT();
    issue_stage(1); CP_COMMIT();
    __syncthreads();   // A preload visible before compute

    const int cv_row = t >> 1, cv_half = t & 1;

    for (int s = 0; s < NST; s++) {
        CP_WAIT1();
        __syncthreads();
        // convert Br[s&1] fp32 -> Bs hi/lo bf16
        {
            const unsigned char* src = dsm + OFF_BR2 + (uint32_t)(s & 1) * 18432u
                                       + cv_row * 144 + cv_half * 64;
            const float4* s4 = (const float4*)src;
            uint4 ph[2], pl[2];
            #pragma unroll
            for (int hq = 0; hq < 2; hq++) {
                float4 va = s4[hq * 2], vb = s4[hq * 2 + 1];
                unsigned h0,l0,h1,l1,h2,l2,h3,l3;
                split2(va.x, va.y, h0, l0); split2(va.z, va.w, h1, l1);
                split2(vb.x, vb.y, h2, l2); split2(vb.z, vb.w, h3, l3);
                ph[hq] = make_uint4(h0, h1, h2, h3);
                pl[hq] = make_uint4(l0, l1, l2, l3);
            }
            uint4* dh = (uint4*)(dsm + OFF_BS2 + cv_row * 80 + cv_half * 32);
            uint4* dl = (uint4*)(dsm + OFF_BS2 + 10240 + cv_row * 80 + cv_half * 32);
            dh[0] = ph[0]; dh[1] = ph[1];
            dl[0] = pl[0]; dl[1] = pl[1];
        }
        __syncthreads();
        // compute: A cols s*32.. vs Bs (3-term hi/lo)
        #pragma unroll
        for (int ks = 0; ks < 2; ks++) {
            unsigned ah[2][4], al[2][4];
            #pragma unroll
            for (int tm = 0; tm < 2; tm++) {
                int row = wm * 32 + tm * 16 + ((lane >> 3) & 1) * 8 + (lane & 7);
                int col = s * 32 + ks * 16 + (lane >> 4) * 8;
                ldm_x4(ah[tm][0], ah[tm][1], ah[tm][2], ah[tm][3],
                       dsm + row * ASTR + col * 2);
                ldm_x4(al[tm][0], al[tm][1], al[tm][2], al[tm][3],
                       dsm + APL + row * ASTR + col * 2);
            }
            unsigned bh[4][2], bl[4][2];
            #pragma unroll
            for (int g = 0; g < 2; g++) {
                int nrow = wn * 32 + g * 16 + (lane >> 4) * 8 + (lane & 7);
                int col  = ks * 16 + ((lane >> 3) & 1) * 8;
                unsigned r0, r1, r2, r3;
                ldm_x4(r0, r1, r2, r3, dsm + OFF_BS2 + nrow * 80 + col * 2);
                bh[g*2+0][0] = r0; bh[g*2+0][1] = r1;
                bh[g*2+1][0] = r2; bh[g*2+1][1] = r3;
                ldm_x4(r0, r1, r2, r3, dsm + OFF_BS2 + 10240 + nrow * 80 + col * 2);
                bl[g*2+0][0] = r0; bl[g*2+0][1] = r1;
                bl[g*2+1][0] = r2; bl[g*2+1][1] = r3;
            }
            #pragma unroll
            for (int tm = 0; tm < 2; tm++)
                #pragma unroll
                for (int tn = 0; tn < 4; tn++) {
                    mma16816(acc[tm][tn], ah[tm], bh[tn][0], bh[tn][1]);
                    mma16816(acc[tm][tn], ah[tm], bl[tn][0], bl[tn][1]);
                    mma16816(acc[tm][tn], al[tm], bh[tn][0], bh[tn][1]);
                }
        }
        __syncthreads();
        if (s + 2 < NST) issue_stage(s + 2);
        CP_COMMIT();
    }

    // ---- epilogue: fp32 split-K partials [split][n][64b] ----
    float* outp = (MODE == 0) ? (is_h ? g_gh : g_gi) : g_cpart;
    const size_t base = (size_t)blockIdx.y * NTOT * 64;
    const int mrow  = wm * 32 + (lane >> 2);
    const int ncol0 = wn * 32 + 2 * (lane & 3);
    #pragma unroll
    for (int tm = 0; tm < 2; tm++) {
        #pragma unroll
        for (int tn = 0; tn < 4; tn++) {
            #pragma unroll
            for (int cc = 0; cc < 2; cc++) {
                int n = n0 + ncol0 + tn * 8 + cc;
                float* o = outp + base + (size_t)n * 64;
                o[mrow + tm * 16]     = acc[tm][tn][cc];
                o[mrow + tm * 16 + 8] = acc[tm][tn][2 + cc];
            }
        }
    }
}
constexpr uint32_t SMALL_SMEM = 92160;

// ---------------- GRU gates ----------------
__global__ void gru_gates(const float* __restrict__ lh, const float* __restrict__ b_ih,
                          const float* __restrict__ b_hh, float* __restrict__ dout)
{
    int idx = blockIdx.x * 256 + threadIdx.x;
    int j = idx >> 6, b = idx & 63;
    float ir = 0.f, iz = 0.f, inn = 0.f, hr = 0.f, hz = 0.f, hn = 0.f;
    #pragma unroll
    for (int s = 0; s < SPL; s++) {
        const float* gi = g_gi + (size_t)s * (3 * H * 64);
        const float* gh = g_gh + (size_t)s * (3 * H * 64);
        ir  += gi[j*64 + b];            hr  += gh[j*64 + b];
        iz  += gi[(H + j)*64 + b];      hz  += gh[(H + j)*64 + b];
        inn += gi[(2*H + j)*64 + b];    hn  += gh[(2*H + j)*64 + b];
    }
    ir += b_ih[j]; iz += b_ih[H + j]; inn += b_ih[2*H + j];
    hr += b_hh[j]; hz += b_hh[H + j]; hn  += b_hh[2*H + j];
    float r = 1.f / (1.f + expf(-(ir + hr)));
    float z = 1.f / (1.f + expf(-(iz + hz)));
    float n = tanhf(inn + r * hn);
    float h = lh[b * H + j];
    float hnew = (1.f - z) * n + z * h;
    g_hnew[b * H + j] = hnew;
    dout[BV + (size_t)b * H + j] = hnew;
}

// ---------------- attention: single-pass per (b, chunk) with online softmax ----------------
__global__ __launch_bounds__(256) void attn_fused(const float* __restrict__ enc)
{
    __shared__ __align__(16) float hn[H];
    __shared__ __align__(16) float4 sbuf[8][256];
    __shared__ float sm[8], sl[8];
    const int t = threadIdx.x, lane = t & 31, w = t >> 5;
    const int sp = blockIdx.x, b = blockIdx.y;

    ((float4*)hn)[t] = ((const float4*)(g_hnew + (size_t)b * H))[t];
    __syncthreads();
    const float4* hn4 = (const float4*)hn;

    float m = -1e30f, l = 0.f;
    float4 ctx[8];
    #pragma unroll
    for (int k = 0; k < 8; k++) ctx[k] = make_float4(0.f, 0.f, 0.f, 0.f);

    for (int i = 0; i < 8; i++) {
        int s = sp * 64 + w * 8 + i;
        const float4* e4 = (const float4*)(enc + ((size_t)b * SEQ + s) * H);
        float4 ev[8];
        float a = 0.f;
        #pragma unroll
        for (int k = 0; k < 8; k++) {
            ev[k] = e4[lane + 32 * k];
            float4 hv = hn4[lane + 32 * k];
            a += ev[k].x*hv.x + ev[k].y*hv.y + ev[k].z*hv.z + ev[k].w*hv.w;
        }
        #pragma unroll
        for (int o = 16; o > 0; o >>= 1) a += __shfl_xor_sync(0xffffffffu, a, o);
        if (a > m) {
            float sc = __expf(m - a);
            l *= sc;
            #pragma unroll
            for (int k = 0; k < 8; k++) {
                ctx[k].x *= sc; ctx[k].y *= sc; ctx[k].z *= sc; ctx[k].w *= sc;
            }
            m = a;
        }
        float p = __expf(a - m);
        l += p;
        #pragma unroll
        for (int k = 0; k < 8; k++) {
            ctx[k].x += p * ev[k].x; ctx[k].y += p * ev[k].y;
            ctx[k].z += p * ev[k].z; ctx[k].w += p * ev[k].w;
        }
    }

    if (lane == 0) { sm[w] = m; sl[w] = l; }
    __syncthreads();
    float M = -1e30f;
    #pragma unroll
    for (int w2 = 0; w2 < 8; w2++) M = fmaxf(M, sm[w2]);
    float e = __expf(m - M);
    #pragma unroll
    for (int k = 0; k < 8; k++) {
        float4 v = ctx[k];
        sbuf[w][lane + 32 * k] = make_float4(v.x * e, v.y * e, v.z * e, v.w * e);
    }
    float L = 0.f;
    #pragma unroll
    for (int w2 = 0; w2 < 8; w2++) L += sl[w2] * __expf(sm[w2] - M);
    __syncthreads();

    float4 acc = make_float4(0.f, 0.f, 0.f, 0.f);
    #pragma unroll
    for (int w2 = 0; w2 < 8; w2++) {
        float4 v = sbuf[w2][t];
        acc.x += v.x; acc.y += v.y; acc.z += v.z; acc.w += v.w;
    }
    *(float4*)(g_pctx + ((size_t)(b * 16 + sp)) * H + t * 4) = acc;
    if (t == 0) { g_pm[b * 16 + sp] = M; g_pl[b * 16 + sp] = L; }
}

// ---------------- attention combine: grid (8, 64), 2 chunks x 32 cols per CTA ----------
__global__ __launch_bounds__(256) void attn_combine()
{
    __shared__ __align__(16) float4 red[8][32];
    const int b = blockIdx.y, t = threadIdx.x;
    const int grp = t >> 5;            // chunk group 0..7 (2 chunks each)
    const int col = t & 31;            // float4 column within this CTA's span
    const int j4 = (blockIdx.x * 32 + col) * 4;

    float M = -1e30f;
    #pragma unroll
    for (int c = 0; c < 16; c++) M = fmaxf(M, g_pm[b * 16 + c]);
    float L = 0.f;
    float e[2];
    #pragma unroll
    for (int c = 0; c < 16; c++) {
        float ec = __expf(g_pm[b * 16 + c] - M);
        L += g_pl[b * 16 + c] * ec;
        if ((c >> 1) == grp) e[c & 1] = ec;
    }
    float inv = 1.f / L;

    float4 acc = make_float4(0.f, 0.f, 0.f, 0.f);
    #pragma unroll
    for (int k = 0; k < 2; k++) {
        int c = grp * 2 + k;
        float4 v = *(const float4*)(g_pctx + ((size_t)(b * 16 + c)) * H + j4);
        float wv = e[k];
        acc.x += wv * v.x; acc.y += wv * v.y; acc.z += wv * v.z; acc.w += wv * v.w;
    }
    red[grp][col] = acc;
    __syncthreads();
    if (grp == 0) {
        #pragma unroll
        for (int g = 1; g < 8; g++) {
            float4 v = red[g][col];
            acc.x += v.x; acc.y += v.y; acc.z += v.z; acc.w += v.w;
        }
        *(float4*)(g_ctx + (size_t)b * H + j4) =
            make_float4(acc.x * inv, acc.y * inv, acc.z * inv, acc.w * inv);
    }
}

// ---------------- concat-gemm combine: bias + tanh -> bf16 A ----------------
__global__ void cat_combine(const float* __restrict__ cbias)
{
    int idx = blockIdx.x * 256 + threadIdx.x;
    int n = idx >> 6, b = idx & 63;
    float s = cbias[n];
    #pragma unroll
    for (int sp = 0; sp < CATSPL; sp++) s += g_cpart[((size_t)sp * H + n) * 64 + b];
    g_co_bf[b * H + n] = __float2bfloat16(tanhf(s));
}

// ---------------- output GEMM: 3-deep cp.async ring, early issue, 2 syncs/stage --------
// smem: As (single, 64x80B) @0 : 5120 | Bs (single, 128x80B) @5120 : 10240
//       Braw (fp32, 3 stages, 128x144B) @15360 : 55296 | bias @70656 : 512
constexpr int KC = 32;
constexpr int NST32 = H / KC;                 // 32 stages
constexpr uint32_t OFF_AS = 0;
constexpr uint32_t OFF_BS = 5120;
constexpr uint32_t OFF_BR = 15360;
constexpr uint32_t BR_STG = 18432;
constexpr uint32_t OFF_BIAS = 70656;
constexpr uint32_t OUT_SMEM = 71168;

__global__ __launch_bounds__(256, 3) void out_gemm_cp(const float* __restrict__ ow,
                                                      const float* __restrict__ ob,
                                                      float* __restrict__ dout)
{
    extern __shared__ __align__(16) unsigned char dsm[];
    const uint32_t sbase = (uint32_t)__cvta_generic_to_shared(dsm);
    const int t = threadIdx.x, lane = t & 31, warp = t >> 5;
    const int n0 = blockIdx.x * NB;
    const int wm = warp & 1, wn = warp >> 1;     // warp tile: M32 x N32

    if (t < NB) {
        int n = n0 + t;
        ((float*)(dsm + OFF_BIAS))[t] = (n < V) ? ob[n] : 0.f;
    }

    // A loader (plain LDG, L2-resident; 1 stage ahead in regs)
    const int a_row = t >> 2, a_seg = t & 3;
    const uint32_t a_sts = OFF_AS + (uint32_t)(a_row * 80 + a_seg * 16);
    const __nv_bfloat16* a_src = g_co_bf + a_row * H + a_seg * 8;
    // B raw loader (cp.async, 3-buffer ring)
    uint32_t br_doff[4]; const float* br_src[4];
    #pragma unroll
    for (int j = 0; j < 4; j++) {
        int c = t + 256 * j;
        int row = c >> 3, seg = c & 7;
        br_doff[j] = OFF_BR + (uint32_t)(row * 144 + seg * 16);
        int gr = n0 + row; if (gr >= V) gr = V - 1;
        br_src[j] = ow + (size_t)gr * 1024 + seg * 4;
    }
    auto issueB = [&](int s) {
        const uint32_t stg = (uint32_t)(s % 3);
        #pragma unroll
        for (int j = 0; j < 4; j++)
            cp16(sbase + br_doff[j] + stg * BR_STG, br_src[j] + s * KC);
    };

    float acc[2][4][4];
    #pragma unroll
    for (int i = 0; i < 2; i++)
        #pragma unroll
        for (int j = 0; j < 4; j++)
            #pragma unroll
            for (int r = 0; r < 4; r++) acc[i][j][r] = 0.f;

    uint4 aregs = *(const uint4*)(a_src);          // A(0)
    issueB(0); CP_COMMIT();
    issueB(1); CP_COMMIT();

    const int cv_row = t >> 1, cv_half = t & 1;

    for (int s = 0; s < NST32; s++) {
        CP_WAIT1();
        __syncthreads();                            // (a) raw[s] visible; prev compute done

        // STS A(s) from regs
        *(uint4*)(dsm + a_sts) = aregs;
        // convert Braw[s%3] fp32 -> Bs bf16
        {
            const unsigned char* src = dsm + OFF_BR + (uint32_t)(s % 3) * BR_STG
                                       + cv_row * 144 + cv_half * 64;
            const float4* s4 = (const float4*)src;
            float4 v0 = s4[0], v1 = s4[1], v2 = s4[2], v3 = s4[3];
            uint4 p0 = make_uint4(pack_bf2(v0.x, v0.y), pack_bf2(v0.z, v0.w),
                                  pack_bf2(v1.x, v1.y), pack_bf2(v1.z, v1.w));
            uint4 p1 = make_uint4(pack_bf2(v2.x, v2.y), pack_bf2(v2.z, v2.w),
                                  pack_bf2(v3.x, v3.y), pack_bf2(v3.z, v3.w));
            uint4* dst = (uint4*)(dsm + OFF_BS + cv_row * 80 + cv_half * 32);
            dst[0] = p0; dst[1] = p1;
        }
        // early issue of stage s+2 (ring slot (s+2)%3 was freed last iteration)
        if (s + 2 < NST32) issueB(s + 2);
        CP_COMMIT();
        // prefetch A(s+1) into regs (L2 hit)
        {
            int kA = (s + 1 < NST32) ? (s + 1) * KC : 0;
            aregs = *(const uint4*)(a_src + kA);
        }
        __syncthreads();                            // (b) As/Bs ready

        // compute stage s
        #pragma unroll
        for (int ks = 0; ks < 2; ks++) {
            unsigned afr[2][4];
            #pragma unroll
            for (int tm = 0; tm < 2; tm++) {
                int row = wm * 32 + tm * 16 + ((lane >> 3) & 1) * 8 + (lane & 7);
                int col = ks * 16 + (lane >> 4) * 8;
                ldm_x4(afr[tm][0], afr[tm][1], afr[tm][2], afr[tm][3],
                       dsm + OFF_AS + row * 80 + col * 2);
            }
            unsigned bfr[4][2];
            #pragma unroll
            for (int g = 0; g < 2; g++) {
                int nrow = wn * 32 + g * 16 + (lane >> 4) * 8 + (lane & 7);
                int col  = ks * 16 + ((lane >> 3) & 1) * 8;
                unsigned r0, r1, r2, r3;
                ldm_x4(r0, r1, r2, r3, dsm + OFF_BS + nrow * 80 + col * 2);
                bfr[g*2+0][0] = r0; bfr[g*2+0][1] = r1;
                bfr[g*2+1][0] = r2; bfr[g*2+1][1] = r3;
            }
            #pragma unroll
            for (int tm = 0; tm < 2; tm++)
                #pragma unroll
                for (int tn = 0; tn < 4; tn++)
                    mma16816(acc[tm][tn], afr[tm], bfr[tn][0], bfr[tn][1]);
        }
    }
    __syncthreads();    // protect As-region reuse below

    // epilogue: write logits + per-(row, block) online-softmax partials
    const float* sbias = (const float*)(dsm + OFF_BIAS);
    float2* part = (float2*)dsm;                 // reuse As region (2KB)
    const int mrow  = wm * 32 + (lane >> 2);
    const int ncol0 = n0 + wn * 32 + 2 * (lane & 3);

    float pmv[4], plv[4];
    #pragma unroll
    for (int i = 0; i < 4; i++) { pmv[i] = -1e30f; plv[i] = 0.f; }

    #pragma unroll
    for (int tm = 0; tm < 2; tm++) {
        #pragma unroll
        for (int tn = 0; tn < 4; tn++) {
            int r = mrow + tm * 16;
            int c = ncol0 + tn * 8;
            #pragma unroll
            for (int cc = 0; cc < 2; cc++) {
                if (c + cc < V) {
                    float bb = sbias[c + cc - n0];
                    float v0 = acc[tm][tn][cc]     + bb;    // row r
                    float v1 = acc[tm][tn][2 + cc] + bb;    // row r+8
                    dout[(size_t)r * V + c + cc]       = v0;
                    dout[(size_t)(r + 8) * V + c + cc] = v1;
                    int i0 = 2 * tm, i1 = 2 * tm + 1;
                    if (v0 > pmv[i0]) { plv[i0] *= __expf(pmv[i0] - v0); pmv[i0] = v0; }
                    plv[i0] += __expf(v0 - pmv[i0]);
                    if (v1 > pmv[i1]) { plv[i1] *= __expf(pmv[i1] - v1); pmv[i1] = v1; }
                    plv[i1] += __expf(v1 - pmv[i1]);
                }
            }
        }
    }
    // reduce across the 4 lanes sharing each row
    #pragma unroll
    for (int i = 0; i < 4; i++) {
        #pragma unroll
        for (int off = 1; off <= 2; off <<= 1) {
            float om = __shfl_xor_sync(0xffffffffu, pmv[i], off);
            float ol = __shfl_xor_sync(0xffffffffu, plv[i], off);
            float nm = fmaxf(pmv[i], om);
            plv[i] = plv[i] * __expf(pmv[i] - nm) + ol * __expf(om - nm);
            pmv[i] = nm;
        }
    }
    if ((lane & 3) == 0) {
        #pragma unroll
        for (int i = 0; i < 4; i++) {
            int row = wm * 32 + (lane >> 2) + (i & 1) * 8 + (i >> 1) * 16;
            part[row * 4 + wn] = make_float2(pmv[i], plv[i]);
        }
    }
    __syncthreads();
    if (t < 64) {
        float m = -1e30f, l = 0.f;
        #pragma unroll
        for (int k = 0; k < 4; k++) {
            float2 p = part[t * 4 + k];
            float nm = fmaxf(m, p.x);
            l = l * __expf(m - nm) + p.y * __expf(p.x - nm);
            m = nm;
        }
        g_plse[t * NBLKP + blockIdx.x] = make_float2(m, l);
    }
}

// ---------------- final: reduce lse partials (redundantly per CTA) + subtract ----------
constexpr int SUBSPAN = 6288;   // 8 * 6288 >= V
__global__ __launch_bounds__(256) void sub_final(float* __restrict__ dout)
{
    __shared__ float rm[256], rl[256];
    const int b = blockIdx.y, cx = blockIdx.x, t = threadIdx.x;
    float m = -1e30f, l = 0.f;
    for (int i = t; i < NBLK; i += 256) {
        float2 p = g_plse[b * NBLKP + i];
        float nm = fmaxf(m, p.x);
        l = l * __expf(m - nm) + p.y * __expf(p.x - nm);
        m = nm;
    }
    rm[t] = m; rl[t] = l; __syncthreads();
    for (int o = 128; o > 0; o >>= 1) {
        if (t < o) {
            float m2 = fmaxf(rm[t], rm[t + o]);
            rl[t] = rl[t] * __expf(rm[t] - m2) + rl[t + o] * __expf(rm[t + o] - m2);
            rm[t] = m2;
        }
        __syncthreads();
    }
    float lse = rm[0] + logf(rl[0]);
    float* row = dout + (size_t)b * V;
    int end = cx * SUBSPAN + SUBSPAN; if (end > V) end = V;
    for (int v = cx * SUBSPAN + t; v < end; v += 256) {
        float x = __ldcs(row + v);
        __stcs(row + v, x - lse);
    }
}

// ---------------- launch ----------------
extern "C" void kernel_launch(void* const* d_in, const int* in_sizes, int n_in,
                              void* d_out, int out_size)
{
    const int*   seq = (const int*)  d_in[0];
    const float* lh  = (const float*)d_in[1];
    const float* enc = (const float*)d_in[2];
    const float* emb = (const float*)d_in[3];
    const float* wih = (const float*)d_in[4];
    const float* whh = (const float*)d_in[5];
    const float* bih = (const float*)d_in[6];
    const float* bhh = (const float*)d_in[7];
    const float* cw  = (const float*)d_in[8];
    const float* cb  = (const float*)d_in[9];
    const float* ow  = (const float*)d_in[10];
    const float* ob  = (const float*)d_in[11];
    float* dout = (float*)d_out;
    (void)in_sizes; (void)n_in; (void)out_size;

    static bool attr_done = false;
    if (!attr_done) {
        cudaFuncSetAttribute(out_gemm_cp,
                             cudaFuncAttributeMaxDynamicSharedMemorySize, OUT_SMEM);
        cudaFuncSetAttribute(mma_small<0, 3*H, H, SPL>,
                             cudaFuncAttributeMaxDynamicSharedMemorySize, SMALL_SMEM);
        cudaFuncSetAttribute(mma_small<2, H, 2*H, CATSPL>,
                             cudaFuncAttributeMaxDynamicSharedMemorySize, SMALL_SMEM);
        attr_done = true;
    }

    // GRU gate GEMMs on tensor cores, hi/lo bf16 (z=0: emb path, z=1: hidden path)
    mma_small<0, 3*H, H, SPL><<<dim3(24, SPL, 2), 256, SMALL_SMEM>>>(seq, emb, lh, wih, whh);
    gru_gates<<<256, 256>>>(lh, bih, bhh, dout);

    // attention (single HBM pass) + combine
    attn_fused<<<dim3(16, 64), 256>>>(enc);
    attn_combine<<<dim3(8, 64), 256>>>();

    // concat GEMM on tensor cores, hi/lo bf16 + tanh -> bf16
    mma_small<2, H, 2*H, CATSPL><<<dim3(8, CATSPL), 256, SMALL_SMEM>>>(nullptr, nullptr, nullptr, cw, nullptr);
    cat_combine<<<256, 256>>>(cb);

    // output GEMM (3-deep cp.async ring, 3 CTA/SM) -> logits + lse partials
    out_gemm_cp<<<NBLK, 256, OUT_SMEM>>>(ow, ob, dout);

    // reduce partials + subtract (full-chip)
    sub_final<<<dim3(8, 64), 256>>>(dout);
}